// round 1
// baseline (speedup 1.0000x reference)
#include <cuda_runtime.h>
#include <cstdint>

// DynamicMaskHead: per-match 3-layer pixel MLP (10->8 gelu ->8 gelu ->1).
// Strategy: packed fp32x2 (2 pixels per FFMA2) on the fma pipe, weights
// duplicated (w,w) in shared as 64-bit words (one broadcast LDS.64 feeds the
// packed FMA directly), gelu via tanh.approx.f32 (MUFU pipe, overlapped).

typedef unsigned long long u64t;

#define TPB 128   // threads per block
#define NP  4     // pixel-pairs per thread (8 pixels/thread)

__device__ __forceinline__ u64t pack2(float lo, float hi) {
    u64t r; asm("mov.b64 %0, {%1, %2};" : "=l"(r) : "f"(lo), "f"(hi)); return r;
}
__device__ __forceinline__ void unpack2(u64t v, float& lo, float& hi) {
    asm("mov.b64 {%0, %1}, %2;" : "=f"(lo), "=f"(hi) : "l"(v));
}
__device__ __forceinline__ u64t fma2(u64t a, u64t b, u64t c) {
    u64t d; asm("fma.rn.f32x2 %0, %1, %2, %3;" : "=l"(d) : "l"(a), "l"(b), "l"(c));
    return d;
}
__device__ __forceinline__ u64t mul2(u64t a, u64t b) {
    u64t d; asm("mul.rn.f32x2 %0, %1, %2;" : "=l"(d) : "l"(a), "l"(b));
    return d;
}
__device__ __forceinline__ float tanh_hw(float x) {
    float r; asm("tanh.approx.f32 %0, %1;" : "=f"(r) : "f"(x)); return r;
}

// gelu(x) = 0.5 x (1 + tanh(0.7978845608 (x + 0.044715 x^3))), packed over 2 px
__device__ __forceinline__ u64t gelu2(u64t x, u64t K0, u64t K1, u64t H2) {
    u64t t = mul2(x, x);
    u64t s = fma2(K1, t, K0);
    u64t u = mul2(x, s);
    float ua, ub; unpack2(u, ua, ub);
    u64t T = pack2(tanh_hw(ua), tanh_hw(ub));
    u64t hx = mul2(x, H2);
    return fma2(hx, T, hx);   // 0.5x*T + 0.5x
}

__global__ void __launch_bounds__(TPB)
dmh_kernel(const float* __restrict__ E,
           const float* __restrict__ theta,
           const float* __restrict__ centers,
           const int*   __restrict__ bidx,
           float*       __restrict__ out)
{
    __shared__ u64t sw[169];           // theta row, each weight duplicated (w,w)

    const int m   = blockIdx.y;
    const int tid = threadIdx.x;

    for (int i = tid; i < 169; i += TPB) {
        float w = __ldg(&theta[m * 169 + i]);
        sw[i] = pack2(w, w);
    }
    __syncthreads();

    const int   b  = __ldg(&bidx[m]);
    const float cx = __ldg(&centers[2 * m + 0]);
    const float cy = __ldg(&centers[2 * m + 1]);
    const float* Eb = E + ((size_t)b << 19);   // b * 8 * 65536

    const u64t K0 = pack2(0.7978845608f, 0.7978845608f);
    const u64t K1 = pack2(0.03567740814f, 0.03567740814f);  // 0.044715*k0
    const u64t H2 = pack2(0.5f, 0.5f);

    // ---- gather inputs: 8 E channels + 2 rel-coord channels, NP pairs ----
    u64t X[NP][10];
    int  pixk[NP];
#pragma unroll
    for (int k = 0; k < NP; k++) {
        int p2  = blockIdx.x * (TPB * NP) + k * TPB + tid;  // pair index
        int pix = p2 << 1;
        pixk[k] = pix;
        int y = pix >> 8, x = pix & 255;
        float fy  = fmaf((float)y, 1.0f / 256.0f, 0.5f / 256.0f) - cy;
        float fx0 = fmaf((float)x, 1.0f / 256.0f, 0.5f / 256.0f) - cx;
        float fx1 = fx0 + 1.0f / 256.0f;
#pragma unroll
        for (int c = 0; c < 8; c++) {
            float2 e = *reinterpret_cast<const float2*>(Eb + ((size_t)c << 16) + pix);
            X[k][c] = pack2(e.x, e.y);
        }
        X[k][8] = pack2(fx0, fx1);   // grid_x - cx
        X[k][9] = pack2(fy,  fy);    // grid_y - cy
    }

    // ---- layer 1: 10 -> 8, w1[o,i] = theta[o*10+i], b1 = theta[80+o] ----
    u64t H[NP][8];
#pragma unroll
    for (int o = 0; o < 8; o++) {
        u64t bo = sw[80 + o];
#pragma unroll
        for (int k = 0; k < NP; k++) H[k][o] = bo;
#pragma unroll
        for (int i = 0; i < 10; i++) {
            u64t w = sw[o * 10 + i];
#pragma unroll
            for (int k = 0; k < NP; k++) H[k][o] = fma2(w, X[k][i], H[k][o]);
        }
    }
#pragma unroll
    for (int k = 0; k < NP; k++)
#pragma unroll
        for (int o = 0; o < 8; o++) H[k][o] = gelu2(H[k][o], K0, K1, H2);

    // ---- layer 2: 8 -> 8, w2[o,i] = theta[88+o*8+i], b2 = theta[152+o] ----
    u64t G[NP][8];
#pragma unroll
    for (int o = 0; o < 8; o++) {
        u64t bo = sw[152 + o];
#pragma unroll
        for (int k = 0; k < NP; k++) G[k][o] = bo;
#pragma unroll
        for (int i = 0; i < 8; i++) {
            u64t w = sw[88 + o * 8 + i];
#pragma unroll
            for (int k = 0; k < NP; k++) G[k][o] = fma2(w, H[k][i], G[k][o]);
        }
    }
#pragma unroll
    for (int k = 0; k < NP; k++)
#pragma unroll
        for (int o = 0; o < 8; o++) G[k][o] = gelu2(G[k][o], K0, K1, H2);

    // ---- layer 3: 8 -> 1, w3[i] = theta[160+i], b3 = theta[168] ----
    float* outm = out + ((size_t)m << 16);
#pragma unroll
    for (int k = 0; k < NP; k++) {
        u64t acc = sw[168];
#pragma unroll
        for (int i = 0; i < 8; i++) acc = fma2(sw[160 + i], G[k][i], acc);
        float a0, a1; unpack2(acc, a0, a1);
        *reinterpret_cast<float2*>(outm + pixk[k]) = make_float2(a0, a1);
    }
}

extern "C" void kernel_launch(void* const* d_in, const int* in_sizes, int n_in,
                              void* d_out, int out_size)
{
    const float* E       = (const float*)d_in[0];
    const float* theta   = (const float*)d_in[1];
    const float* centers = (const float*)d_in[2];
    const int*   bidx    = (const int*)d_in[3];

    // 65536 pixels/match, 1024 pixels/block -> 64 blocks/match, 256 matches
    dim3 grid(65536 / (TPB * NP * 2), 256, 1);
    dmh_kernel<<<grid, TPB>>>(E, theta, centers, bidx, (float*)d_out);
}